// round 1
// baseline (speedup 1.0000x reference)
#include <cuda_runtime.h>

#define BSZ    32768
#define OBSD   17
#define ACTD   6
#define INDIM  23
#define HDIM   256
#define NQ     10
#define TB     64
#define NTHREADS 256

// ---- shared memory layout (float offsets) ----
#define OFF_H1T   0                 // h1 transposed [HDIM][TB]  : 256*64 = 16384
#define OFF_XS    16384             // x tile [TB][25] (stride 25): 1600
#define OFF_B1    17984             // 256
#define OFF_B2    18240             // 256
#define OFF_W3    18496             // 256
#define OFF_U     18752             // union: W1s (23*256=5888)  OR  W2s(2*16*128=4096)+red(512)
#define OFF_W2S   OFF_U
#define OFF_RED   (OFF_U + 4096)
#define SMEM_FLOATS (OFF_U + 5888)  // 24640
#define SMEM_BYTES  (SMEM_FLOATS * 4)  // 98560 bytes -> 2 CTAs/SM

typedef unsigned long long ull;

__device__ __forceinline__ ull pack2(float x, float y) {
    ull r;
    asm("mov.b64 %0, {%1, %2};" : "=l"(r) : "f"(x), "f"(y));
    return r;
}
__device__ __forceinline__ void unpack2(ull v, float& lo, float& hi) {
    asm("mov.b64 {%0, %1}, %2;" : "=f"(lo), "=f"(hi) : "l"(v));
}
// packed dual-FMA: d.lo += a.lo*b.lo ; d.hi += a.hi*b.hi
__device__ __forceinline__ void fma2(ull& d, ull a, ull b) {
    asm("fma.rn.f32x2 %0, %1, %2, %0;" : "+l"(d) : "l"(a), "l"(b));
}

__global__ void __launch_bounds__(NTHREADS, 2)
qens_fused_kernel(const float* __restrict__ state,
                  const float* __restrict__ action,
                  const float* __restrict__ W1,
                  const float* __restrict__ b1,
                  const float* __restrict__ W2,
                  const float* __restrict__ b2,
                  const float* __restrict__ W3,
                  const float* __restrict__ b3,
                  float* __restrict__ out)
{
    extern __shared__ float sm[];
    const int tid = threadIdx.x;
    const int n   = blockIdx.y;
    const int gb0 = blockIdx.x * TB;

    float* h1T = sm + OFF_H1T;   // [h][r], stride TB
    float* xs  = sm + OFF_XS;    // [r][k], stride 25 (conflict-free)
    float* b1s = sm + OFF_B1;
    float* b2s = sm + OFF_B2;
    float* w3s = sm + OFF_W3;
    float* W1s = sm + OFF_U;     // [k][c], stride 256 (layer1 phase only)
    float* W2s = sm + OFF_W2S;   // double buffer [2][16][128]
    float* red = sm + OFF_RED;   // [8 warps][64 rows]

    // ---- stage x tile, biases, W1 ----
    for (int idx = tid; idx < TB * INDIM; idx += NTHREADS) {
        int r = idx / INDIM, k = idx % INDIM;
        float v = (k < OBSD) ? state[(gb0 + r) * OBSD + k]
                             : action[(gb0 + r) * ACTD + (k - OBSD)];
        xs[r * 25 + k] = v;
    }
    if (tid < HDIM) {
        b1s[tid] = b1[n * HDIM + tid];
        b2s[tid] = b2[n * HDIM + tid];
        w3s[tid] = W3[n * HDIM + tid];   // W3 is [N,H,1]
    }
    const float* W1n = W1 + n * INDIM * HDIM;
    for (int idx = tid; idx < INDIM * HDIM; idx += NTHREADS)
        W1s[idx] = W1n[idx];
    __syncthreads();

    // ---- layer 1: h1T[c][r] = relu(sum_k x[r][k]*W1[k][c] + b1[c]) ----
    // thread owns one row r (lanes = consecutive rows -> conflict-free STS),
    // loops over a 64-column group.
    {
        const int r   = tid & 63;
        const int cg2 = tid >> 6;     // 0..3
        float xr[INDIM];
        #pragma unroll
        for (int k = 0; k < INDIM; k++) xr[k] = xs[r * 25 + k];
        const int cbase = cg2 * 64;
        #pragma unroll 4
        for (int cc = 0; cc < 64; cc++) {
            int c = cbase + cc;
            float acc = b1s[c];
            #pragma unroll
            for (int k = 0; k < INDIM; k++)
                acc = fmaf(xr[k], W1s[k * HDIM + c], acc);  // W1s: warp-uniform -> broadcast
            h1T[c * TB + r] = fmaxf(acc, 0.0f);
        }
    }
    __syncthreads();   // h1T ready; W1s region now reused as W2s/red

    // ---- layer 2 + 3 fused ----
    // warp handles all 64 rows x 16 cols; thread: 8 rows (4 interleaved pairs) x 4 cols.
    // row pairs for thread: (2rg+16j, 2rg+16j+1), j=0..3  -> LDS.64 conflict-free.
    const int lane = tid & 31;
    const int warp = tid >> 5;
    const int rg   = lane >> 2;       // 0..7
    const int cg   = lane & 3;        // 0..3
    const int rbase = 2 * rg;
    const float*  W2n  = W2 + n * HDIM * HDIM;
    const float4* W2n4 = reinterpret_cast<const float4*>(W2n);   // row stride 64 float4

    const int skk  = tid >> 5;        // staging: k-row 0..7 (and +8)
    const int scc4 = tid & 31;        // staging: float4 col within 128

    float totalr = 0.0f;              // meaningful for tid < 64

    #pragma unroll 1
    for (int chunk = 0; chunk < 2; chunk++) {
        const int cb4 = chunk * 32;   // col chunk base in float4 units (0 or 128/4)

        // stage buffer 0 (k = 0..15)
        {
            float4 v0 = W2n4[(skk)     * 64 + cb4 + scc4];
            float4 v1 = W2n4[(skk + 8) * 64 + cb4 + scc4];
            *reinterpret_cast<float4*>(W2s + skk * 128 + scc4 * 4)       = v0;
            *reinterpret_cast<float4*>(W2s + (skk + 8) * 128 + scc4 * 4) = v1;
        }
        __syncthreads();

        ull acc[4][4];
        #pragma unroll
        for (int j = 0; j < 4; j++)
            #pragma unroll
            for (int l = 0; l < 4; l++) acc[j][l] = 0ULL;

        const int wcol = warp * 16 + cg * 4;   // word offset within 128-col chunk

        #pragma unroll 1
        for (int k0 = 0; k0 < HDIM; k0 += 16) {
            // prefetch next 16 k-rows into registers (hidden behind compute)
            float4 p0, p1;
            const bool pref = (k0 + 16) < HDIM;
            if (pref) {
                p0 = W2n4[(k0 + 16 + skk) * 64 + cb4 + scc4];
                p1 = W2n4[(k0 + 24 + skk) * 64 + cb4 + scc4];
            }
            const int cur = (k0 >> 4) & 1;
            const float* wb = W2s + cur * 2048;

            #pragma unroll
            for (int kk = 0; kk < 16; kk++) {
                const int k = k0 + kk;
                const float* h1k = h1T + k * TB + rbase;
                ull a0 = *reinterpret_cast<const ull*>(h1k);
                ull a1 = *reinterpret_cast<const ull*>(h1k + 16);
                ull a2 = *reinterpret_cast<const ull*>(h1k + 32);
                ull a3 = *reinterpret_cast<const ull*>(h1k + 48);
                float4 w = *reinterpret_cast<const float4*>(wb + kk * 128 + wcol);
                ull w0 = pack2(w.x, w.x);
                ull w1 = pack2(w.y, w.y);
                ull w2p = pack2(w.z, w.z);
                ull w3p = pack2(w.w, w.w);
                fma2(acc[0][0], a0, w0); fma2(acc[0][1], a0, w1);
                fma2(acc[0][2], a0, w2p); fma2(acc[0][3], a0, w3p);
                fma2(acc[1][0], a1, w0); fma2(acc[1][1], a1, w1);
                fma2(acc[1][2], a1, w2p); fma2(acc[1][3], a1, w3p);
                fma2(acc[2][0], a2, w0); fma2(acc[2][1], a2, w1);
                fma2(acc[2][2], a2, w2p); fma2(acc[2][3], a2, w3p);
                fma2(acc[3][0], a3, w0); fma2(acc[3][1], a3, w1);
                fma2(acc[3][2], a3, w2p); fma2(acc[3][3], a3, w3p);
            }

            if (pref) {
                const int nxt = cur ^ 1;
                *reinterpret_cast<float4*>(W2s + nxt * 2048 + skk * 128 + scc4 * 4)       = p0;
                *reinterpret_cast<float4*>(W2s + nxt * 2048 + (skk + 8) * 128 + scc4 * 4) = p1;
            }
            __syncthreads();
        }

        // epilogue: +b2, relu, dot with W3 (layer 3), reduce over columns
        float psum[4][2];
        #pragma unroll
        for (int j = 0; j < 4; j++) {
            float slo = 0.0f, shi = 0.0f;
            #pragma unroll
            for (int l = 0; l < 4; l++) {
                const int c = chunk * 128 + wcol + l;
                float lo, hi;
                unpack2(acc[j][l], lo, hi);
                lo = fmaxf(lo + b2s[c], 0.0f);
                hi = fmaxf(hi + b2s[c], 0.0f);
                slo = fmaf(lo, w3s[c], slo);
                shi = fmaf(hi, w3s[c], shi);
            }
            psum[j][0] = slo; psum[j][1] = shi;
        }
        // reduce across the 4 cg lanes (same rows, different cols)
        #pragma unroll
        for (int j = 0; j < 4; j++)
            #pragma unroll
            for (int h = 0; h < 2; h++) {
                float v = psum[j][h];
                v += __shfl_xor_sync(0xffffffffu, v, 1);
                v += __shfl_xor_sync(0xffffffffu, v, 2);
                psum[j][h] = v;
            }
        if (cg == 0) {
            #pragma unroll
            for (int j = 0; j < 4; j++)
                #pragma unroll
                for (int h = 0; h < 2; h++) {
                    const int r = rbase + 16 * j + h;
                    red[warp * 64 + r] = psum[j][h];
                }
        }
        __syncthreads();
        if (tid < TB) {
            float s = 0.0f;
            #pragma unroll
            for (int w = 0; w < 8; w++) s += red[w * 64 + tid];
            totalr += s;
        }
        __syncthreads();   // red reused next chunk
    }

    if (tid < TB)
        out[n * BSZ + gb0 + tid] = totalr + b3[n];
}

extern "C" void kernel_launch(void* const* d_in, const int* in_sizes, int n_in,
                              void* d_out, int out_size)
{
    const float* state  = (const float*)d_in[0];
    const float* action = (const float*)d_in[1];
    const float* W1     = (const float*)d_in[2];
    const float* b1     = (const float*)d_in[3];
    const float* W2     = (const float*)d_in[4];
    const float* b2     = (const float*)d_in[5];
    const float* W3     = (const float*)d_in[6];
    const float* b3     = (const float*)d_in[7];
    float* out = (float*)d_out;

    cudaFuncSetAttribute(qens_fused_kernel,
                         cudaFuncAttributeMaxDynamicSharedMemorySize, SMEM_BYTES);

    dim3 grid(BSZ / TB, NQ);   // 512 batch tiles x 10 ensemble members
    qens_fused_kernel<<<grid, NTHREADS, SMEM_BYTES>>>(
        state, action, W1, b1, W2, b2, W3, b3, out);
}

// round 2
// speedup vs baseline: 1.0027x; 1.0027x over previous
#include <cuda_runtime.h>

#define BSZ    32768
#define OBSD   17
#define ACTD   6
#define INDIM  23
#define HDIM   256
#define NQ     10
#define TB     64
#define NTHREADS 256

// ---- shared memory layout (float offsets) ----
#define OFF_H1T   0                 // h1 transposed [HDIM][TB]  : 256*64 = 16384
#define OFF_XS    16384             // x tile [TB][25] (stride 25): 1600
#define OFF_B1    17984             // 256
#define OFF_B2    18240             // 256
#define OFF_W3    18496             // 256
#define OFF_U     18752             // union: W1s (23*256=5888)  OR  W2s(2*16*128=4096)+red(512)
#define OFF_W2S   OFF_U
#define OFF_RED   (OFF_U + 4096)
#define SMEM_FLOATS (OFF_U + 5888)  // 24640
#define SMEM_BYTES  (SMEM_FLOATS * 4)  // 98560 bytes -> 2 CTAs/SM

typedef unsigned long long ull;

__device__ __forceinline__ ull pack2(float x, float y) {
    ull r;
    asm("mov.b64 %0, {%1, %2};" : "=l"(r) : "f"(x), "f"(y));
    return r;
}
__device__ __forceinline__ void unpack2(ull v, float& lo, float& hi) {
    asm("mov.b64 {%0, %1}, %2;" : "=f"(lo), "=f"(hi) : "l"(v));
}
// packed dual-FMA: d.lo += a.lo*b.lo ; d.hi += a.hi*b.hi
__device__ __forceinline__ void fma2(ull& d, ull a, ull b) {
    asm("fma.rn.f32x2 %0, %1, %2, %0;" : "+l"(d) : "l"(a), "l"(b));
}

__global__ void __launch_bounds__(NTHREADS, 2)
qens_fused_kernel(const float* __restrict__ state,
                  const float* __restrict__ action,
                  const float* __restrict__ W1,
                  const float* __restrict__ b1,
                  const float* __restrict__ W2,
                  const float* __restrict__ b2,
                  const float* __restrict__ W3,
                  const float* __restrict__ b3,
                  float* __restrict__ out)
{
    extern __shared__ float sm[];
    const int tid = threadIdx.x;
    const int n   = blockIdx.y;
    const int gb0 = blockIdx.x * TB;

    float* h1T = sm + OFF_H1T;   // [h][r], stride TB
    float* xs  = sm + OFF_XS;    // [r][k], stride 25 (conflict-free)
    float* b1s = sm + OFF_B1;
    float* b2s = sm + OFF_B2;
    float* w3s = sm + OFF_W3;
    float* W1s = sm + OFF_U;     // [k][c], stride 256 (layer1 phase only)
    float* W2s = sm + OFF_W2S;   // double buffer [2][16][128]
    float* red = sm + OFF_RED;   // [8 warps][64 rows]

    // ---- stage x tile, biases, W1 ----
    for (int idx = tid; idx < TB * INDIM; idx += NTHREADS) {
        int r = idx / INDIM, k = idx % INDIM;
        float v = (k < OBSD) ? state[(gb0 + r) * OBSD + k]
                             : action[(gb0 + r) * ACTD + (k - OBSD)];
        xs[r * 25 + k] = v;
    }
    if (tid < HDIM) {
        b1s[tid] = b1[n * HDIM + tid];
        b2s[tid] = b2[n * HDIM + tid];
        w3s[tid] = W3[n * HDIM + tid];   // W3 is [N,H,1]
    }
    const float* W1n = W1 + n * INDIM * HDIM;
    for (int idx = tid; idx < INDIM * HDIM; idx += NTHREADS)
        W1s[idx] = W1n[idx];
    __syncthreads();

    // ---- layer 1: h1T[c][r] = relu(sum_k x[r][k]*W1[k][c] + b1[c]) ----
    // thread owns one row r (lanes = consecutive rows -> conflict-free STS),
    // loops over a 64-column group.
    {
        const int r   = tid & 63;
        const int cg2 = tid >> 6;     // 0..3
        float xr[INDIM];
        #pragma unroll
        for (int k = 0; k < INDIM; k++) xr[k] = xs[r * 25 + k];
        const int cbase = cg2 * 64;
        #pragma unroll 4
        for (int cc = 0; cc < 64; cc++) {
            int c = cbase + cc;
            float acc = b1s[c];
            #pragma unroll
            for (int k = 0; k < INDIM; k++)
                acc = fmaf(xr[k], W1s[k * HDIM + c], acc);  // W1s: warp-uniform -> broadcast
            h1T[c * TB + r] = fmaxf(acc, 0.0f);
        }
    }
    __syncthreads();   // h1T ready; W1s region now reused as W2s/red

    // ---- layer 2 + 3 fused ----
    // warp handles all 64 rows x 16 cols; thread: 8 rows (4 interleaved pairs) x 4 cols.
    // row pairs for thread: (2rg+16j, 2rg+16j+1), j=0..3  -> LDS.64 conflict-free.
    const int lane = tid & 31;
    const int warp = tid >> 5;
    const int rg   = lane >> 2;       // 0..7
    const int cg   = lane & 3;        // 0..3
    const int rbase = 2 * rg;
    const float*  W2n  = W2 + n * HDIM * HDIM;
    const float4* W2n4 = reinterpret_cast<const float4*>(W2n);   // row stride 64 float4

    const int skk  = tid >> 5;        // staging: k-row 0..7 (and +8)
    const int scc4 = tid & 31;        // staging: float4 col within 128

    float totalr = 0.0f;              // meaningful for tid < 64

    #pragma unroll 1
    for (int chunk = 0; chunk < 2; chunk++) {
        const int cb4 = chunk * 32;   // col chunk base in float4 units (0 or 128/4)

        // stage buffer 0 (k = 0..15)
        {
            float4 v0 = W2n4[(skk)     * 64 + cb4 + scc4];
            float4 v1 = W2n4[(skk + 8) * 64 + cb4 + scc4];
            *reinterpret_cast<float4*>(W2s + skk * 128 + scc4 * 4)       = v0;
            *reinterpret_cast<float4*>(W2s + (skk + 8) * 128 + scc4 * 4) = v1;
        }
        __syncthreads();

        ull acc[4][4];
        #pragma unroll
        for (int j = 0; j < 4; j++)
            #pragma unroll
            for (int l = 0; l < 4; l++) acc[j][l] = 0ULL;

        const int wcol = warp * 16 + cg * 4;   // word offset within 128-col chunk

        #pragma unroll 1
        for (int k0 = 0; k0 < HDIM; k0 += 16) {
            // prefetch next 16 k-rows into registers (hidden behind compute)
            float4 p0, p1;
            const bool pref = (k0 + 16) < HDIM;
            if (pref) {
                p0 = W2n4[(k0 + 16 + skk) * 64 + cb4 + scc4];
                p1 = W2n4[(k0 + 24 + skk) * 64 + cb4 + scc4];
            }
            const int cur = (k0 >> 4) & 1;
            const float* wb = W2s + cur * 2048;

            #pragma unroll
            for (int kk = 0; kk < 16; kk++) {
                const int k = k0 + kk;
                const float* h1k = h1T + k * TB + rbase;
                ull a0 = *reinterpret_cast<const ull*>(h1k);
                ull a1 = *reinterpret_cast<const ull*>(h1k + 16);
                ull a2 = *reinterpret_cast<const ull*>(h1k + 32);
                ull a3 = *reinterpret_cast<const ull*>(h1k + 48);
                float4 w = *reinterpret_cast<const float4*>(wb + kk * 128 + wcol);
                ull w0 = pack2(w.x, w.x);
                ull w1 = pack2(w.y, w.y);
                ull w2p = pack2(w.z, w.z);
                ull w3p = pack2(w.w, w.w);
                fma2(acc[0][0], a0, w0); fma2(acc[0][1], a0, w1);
                fma2(acc[0][2], a0, w2p); fma2(acc[0][3], a0, w3p);
                fma2(acc[1][0], a1, w0); fma2(acc[1][1], a1, w1);
                fma2(acc[1][2], a1, w2p); fma2(acc[1][3], a1, w3p);
                fma2(acc[2][0], a2, w0); fma2(acc[2][1], a2, w1);
                fma2(acc[2][2], a2, w2p); fma2(acc[2][3], a2, w3p);
                fma2(acc[3][0], a3, w0); fma2(acc[3][1], a3, w1);
                fma2(acc[3][2], a3, w2p); fma2(acc[3][3], a3, w3p);
            }

            if (pref) {
                const int nxt = cur ^ 1;
                *reinterpret_cast<float4*>(W2s + nxt * 2048 + skk * 128 + scc4 * 4)       = p0;
                *reinterpret_cast<float4*>(W2s + nxt * 2048 + (skk + 8) * 128 + scc4 * 4) = p1;
            }
            __syncthreads();
        }

        // epilogue: +b2, relu, dot with W3 (layer 3), reduce over columns
        float psum[4][2];
        #pragma unroll
        for (int j = 0; j < 4; j++) {
            float slo = 0.0f, shi = 0.0f;
            #pragma unroll
            for (int l = 0; l < 4; l++) {
                const int c = chunk * 128 + wcol + l;
                float lo, hi;
                unpack2(acc[j][l], lo, hi);
                lo = fmaxf(lo + b2s[c], 0.0f);
                hi = fmaxf(hi + b2s[c], 0.0f);
                slo = fmaf(lo, w3s[c], slo);
                shi = fmaf(hi, w3s[c], shi);
            }
            psum[j][0] = slo; psum[j][1] = shi;
        }
        // reduce across the 4 cg lanes (same rows, different cols)
        #pragma unroll
        for (int j = 0; j < 4; j++)
            #pragma unroll
            for (int h = 0; h < 2; h++) {
                float v = psum[j][h];
                v += __shfl_xor_sync(0xffffffffu, v, 1);
                v += __shfl_xor_sync(0xffffffffu, v, 2);
                psum[j][h] = v;
            }
        if (cg == 0) {
            #pragma unroll
            for (int j = 0; j < 4; j++)
                #pragma unroll
                for (int h = 0; h < 2; h++) {
                    const int r = rbase + 16 * j + h;
                    red[warp * 64 + r] = psum[j][h];
                }
        }
        __syncthreads();
        if (tid < TB) {
            float s = 0.0f;
            #pragma unroll
            for (int w = 0; w < 8; w++) s += red[w * 64 + tid];
            totalr += s;
        }
        __syncthreads();   // red reused next chunk
    }

    if (tid < TB)
        out[n * BSZ + gb0 + tid] = totalr + b3[n];
}

extern "C" void kernel_launch(void* const* d_in, const int* in_sizes, int n_in,
                              void* d_out, int out_size)
{
    const float* state  = (const float*)d_in[0];
    const float* action = (const float*)d_in[1];
    const float* W1     = (const float*)d_in[2];
    const float* b1     = (const float*)d_in[3];
    const float* W2     = (const float*)d_in[4];
    const float* b2     = (const float*)d_in[5];
    const float* W3     = (const float*)d_in[6];
    const float* b3     = (const float*)d_in[7];
    float* out = (float*)d_out;

    cudaFuncSetAttribute(qens_fused_kernel,
                         cudaFuncAttributeMaxDynamicSharedMemorySize, SMEM_BYTES);

    dim3 grid(BSZ / TB, NQ);   // 512 batch tiles x 10 ensemble members
    qens_fused_kernel<<<grid, NTHREADS, SMEM_BYTES>>>(
        state, action, W1, b1, W2, b2, W3, b3, out);
}

// round 4
// speedup vs baseline: 2.4893x; 2.4825x over previous
#include <cuda_runtime.h>
#include <cuda_bf16.h>
#include <stdint.h>

#define NQ     10
#define BSZ    32768
#define NTILES 256

// Pre-split (hi/lo bf16), pre-SW128-swizzled images.
__device__ __nv_bfloat16 g_Ximg[2][NTILES][8192];      // [split][tile][128 rows x 64 k] (128B rows)
__device__ __nv_bfloat16 g_W1img[2][NQ][16384];        // [split][net][256 feat x 64 k]
__device__ __nv_bfloat16 g_W2img[2][NQ][2][4][8192];   // [split][net][nhalf][kchunk][128 n x 64 k]

__device__ __forceinline__ uint32_t smem_u32(const void* p) {
    uint32_t a;
    asm("{ .reg .u64 t; cvta.to.shared.u64 t, %1; cvt.u32.u64 %0, t; }" : "=r"(a) : "l"(p));
    return a;
}
__device__ __forceinline__ uint32_t sw128(uint32_t off) { return off ^ ((off >> 3) & 0x70); }
__device__ __forceinline__ uint32_t cvt2(float hi, float lo) {
    uint32_t r;
    asm("cvt.rn.bf16x2.f32 %0, %1, %2;" : "=r"(r) : "f"(hi), "f"(lo));
    return r;
}
__device__ __forceinline__ void cpasync16(uint32_t dst, const void* src) {
    asm volatile("cp.async.cg.shared.global [%0], [%1], 16;" :: "r"(dst), "l"(src) : "memory");
}
#define CP_COMMIT() asm volatile("cp.async.commit_group;" ::: "memory")
#define CP_WAIT(n)  asm volatile("cp.async.wait_group %0;" :: "n"(n) : "memory")

__device__ __forceinline__ void ldm4(uint32_t r[4], uint32_t addr) {
    asm volatile("ldmatrix.sync.aligned.m8n8.x4.shared.b16 {%0,%1,%2,%3}, [%4];"
        : "=r"(r[0]), "=r"(r[1]), "=r"(r[2]), "=r"(r[3]) : "r"(addr));
}
__device__ __forceinline__ void mma16816(float c[4], const uint32_t a[4],
                                         uint32_t b0, uint32_t b1) {
    asm volatile("mma.sync.aligned.m16n8k16.row.col.f32.bf16.bf16.f32 "
        "{%0,%1,%2,%3}, {%4,%5,%6,%7}, {%8,%9}, {%0,%1,%2,%3};"
        : "+f"(c[0]), "+f"(c[1]), "+f"(c[2]), "+f"(c[3])
        : "r"(a[0]), "r"(a[1]), "r"(a[2]), "r"(a[3]), "r"(b0), "r"(b1));
}

// ============================ prep kernels ============================
__global__ void __launch_bounds__(256) prep_x_kernel(const float* __restrict__ state,
                                                     const float* __restrict__ action) {
    __shared__ __nv_bfloat16 sh[8192];
    __shared__ __nv_bfloat16 sl[8192];
    const int t = blockIdx.x;
    for (int idx = threadIdx.x; idx < 8192; idx += 256) {
        int r = idx >> 6, k = idx & 63;
        int R = t * 128 + r;
        float v = 0.f;
        if (k < 17)      v = state[R * 17 + k];
        else if (k < 23) v = action[R * 6 + (k - 17)];
        __nv_bfloat16 h = __float2bfloat16(v);
        __nv_bfloat16 l = __float2bfloat16(v - __bfloat162float(h));
        uint32_t off = sw128((uint32_t)(r * 128 + k * 2));
        sh[off >> 1] = h;
        sl[off >> 1] = l;
    }
    __syncthreads();
    uint4* d0 = (uint4*)&g_Ximg[0][t][0];
    uint4* d1 = (uint4*)&g_Ximg[1][t][0];
    const uint4* s0 = (const uint4*)sh;
    const uint4* s1 = (const uint4*)sl;
    for (int i = threadIdx.x; i < 1024; i += 256) { d0[i] = s0[i]; d1[i] = s1[i]; }
}

__global__ void __launch_bounds__(256) prep_w1_kernel(const float* __restrict__ W1) {
    __shared__ __nv_bfloat16 s[16384];
    const int n = blockIdx.x;
    for (int pass = 0; pass < 2; pass++) {
        for (int idx = threadIdx.x; idx < 16384; idx += 256) {
            int r = idx >> 6, k = idx & 63;    // r = out feature, k = in dim
            float v = (k < 23) ? W1[(n * 23 + k) * 256 + r] : 0.f;
            __nv_bfloat16 h = __float2bfloat16(v);
            __nv_bfloat16 o = (pass == 0) ? h : __float2bfloat16(v - __bfloat162float(h));
            s[sw128((uint32_t)(r * 128 + k * 2)) >> 1] = o;
        }
        __syncthreads();
        uint4* dst = (uint4*)&g_W1img[pass][n][0];
        const uint4* ss = (const uint4*)s;
        for (int i = threadIdx.x; i < 2048; i += 256) dst[i] = ss[i];
        __syncthreads();
    }
}

__global__ void __launch_bounds__(256) prep_w2_kernel(const float* __restrict__ W2) {
    __shared__ __nv_bfloat16 s[2][8192];
    const int c = blockIdx.x & 3, n = blockIdx.x >> 2;
    const float* src = W2 + n * 65536 + c * 64 * 256;
    for (int pass = 0; pass < 2; pass++) {
        for (int idx = threadIdx.x; idx < 16384; idx += 256) {
            int kk = idx >> 8, nn = idx & 255;   // B[n][k] = W2[k][n]
            float v = src[kk * 256 + nn];
            __nv_bfloat16 h = __float2bfloat16(v);
            __nv_bfloat16 o = (pass == 0) ? h : __float2bfloat16(v - __bfloat162float(h));
            int half = nn >> 7, nl = nn & 127;
            s[half][sw128((uint32_t)(nl * 128 + kk * 2)) >> 1] = o;
        }
        __syncthreads();
        for (int half = 0; half < 2; half++) {
            uint4* dst = (uint4*)&g_W2img[pass][n][half][c][0];
            const uint4* ss = (const uint4*)&s[half][0];
            for (int i = threadIdx.x; i < 1024; i += 256) dst[i] = ss[i];
        }
        __syncthreads();
    }
}

// ============================ main fused kernel ============================
// SMEM byte map (204800 total):
//  [4096, 69632)   W2 stage buffers (2 x 32KB: hi 16K + lo 16K)  | phase1: W1h@4096, W1l@36864
//  [69632, 135168) A2h image (4 kchunks x 16KB)                  | phase1: Xh@69632, Xl@86016
//  [135168,200704) A2l image
//  [200704,...]    b1s, b2s, w3s, red
#define SM_W2BUF 4096
#define SM_W1H   4096
#define SM_W1L   36864
#define SM_A2H   69632
#define SM_XH    69632
#define SM_XL    86016
#define SM_A2L   135168
#define SM_B1    200704
#define SM_B2    201728
#define SM_W3    202752
#define SM_RED   203776
#define SM_TOTAL 204800

__global__ void __launch_bounds__(256, 1)
qens_hmma_kernel(const float* __restrict__ b1, const float* __restrict__ b2,
                 const float* __restrict__ W3, const float* __restrict__ b3,
                 float* __restrict__ out) {
    extern __shared__ char sarr[];
    float* fsm = (float*)sarr;
    const uint32_t sb = smem_u32(sarr);
    const int tid  = threadIdx.x;
    const int wid  = tid >> 5;
    const int lane = tid & 31;
    const int tile = blockIdx.x;
    const int n    = blockIdx.y;

    const int wm = wid & 3, wn = wid >> 2;
    const int Rw = wm * 32;
    // ldmatrix per-lane address components
    const int aRow = (lane & 7) + ((lane >> 3) & 1) * 8;   // A: row-major [row][k]
    const int aCol = (lane >> 4) * 8;
    const int bRow = (lane & 7) + ((lane >> 4) << 3);      // B: [n][k]
    const int bCol = ((lane >> 3) & 1) * 8;
    const int q  = lane >> 2;
    const int s2 = (lane & 3) * 2;

    // ---- stage phase-1 operands via cp.async ----
    {
        const char* xh = (const char*)&g_Ximg[0][tile][0];
        const char* xl = (const char*)&g_Ximg[1][tile][0];
        for (int i = tid; i < 1024; i += 256) {
            cpasync16(sb + SM_XH + i * 16, xh + i * 16);
            cpasync16(sb + SM_XL + i * 16, xl + i * 16);
        }
        const char* w1h = (const char*)&g_W1img[0][n][0];
        const char* w1l = (const char*)&g_W1img[1][n][0];
        for (int i = tid; i < 2048; i += 256) {
            cpasync16(sb + SM_W1H + i * 16, w1h + i * 16);
            cpasync16(sb + SM_W1L + i * 16, w1l + i * 16);
        }
        CP_COMMIT();
    }
    fsm[SM_B1 / 4 + tid] = b1[n * 256 + tid];
    fsm[SM_B2 / 4 + tid] = b2[n * 256 + tid];
    fsm[SM_W3 / 4 + tid] = W3[n * 256 + tid];
    CP_WAIT(0);
    __syncthreads();

    // ---- layer 1: acc1 = X * W1^T (3-term bf16 split), warp tile 32x128 ----
    float acc1[2][16][4];
    #pragma unroll
    for (int mt = 0; mt < 2; mt++)
        #pragma unroll
        for (int nt = 0; nt < 16; nt++)
            #pragma unroll
            for (int e = 0; e < 4; e++) acc1[mt][nt][e] = 0.f;

    #pragma unroll
    for (int ks = 0; ks < 2; ks++) {
        const int k = ks * 16;
        uint32_t ah[2][4], al[2][4];
        #pragma unroll
        for (int mt = 0; mt < 2; mt++) {
            uint32_t o = sw128((uint32_t)((Rw + mt * 16 + aRow) * 128 + (k + aCol) * 2));
            ldm4(ah[mt], sb + SM_XH + o);
            ldm4(al[mt], sb + SM_XL + o);
        }
        #pragma unroll
        for (int pair = 0; pair < 8; pair++) {
            const int n0 = wn * 128 + pair * 16;
            uint32_t ob = sw128((uint32_t)((n0 + bRow) * 128 + (k + bCol) * 2));
            uint32_t bh[4], bl[4];
            ldm4(bh, sb + SM_W1H + ob);
            ldm4(bl, sb + SM_W1L + ob);
            #pragma unroll
            for (int mt = 0; mt < 2; mt++)
                #pragma unroll
                for (int sub = 0; sub < 2; sub++) {
                    const int nt = pair * 2 + sub;
                    mma16816(acc1[mt][nt], ah[mt], bh[sub * 2], bh[sub * 2 + 1]);
                    mma16816(acc1[mt][nt], ah[mt], bl[sub * 2], bl[sub * 2 + 1]);
                    mma16816(acc1[mt][nt], al[mt], bh[sub * 2], bh[sub * 2 + 1]);
                }
        }
    }
    __syncthreads();   // X / W1 regions now free

    // prefetch W2 stage 0 (npass0, kchunk0) into buf0 while epilogue-1 runs
    {
        const char* srch = (const char*)&g_W2img[0][n][0][0][0];
        const char* srcl = (const char*)&g_W2img[1][n][0][0][0];
        for (int i = tid; i < 1024; i += 256) {
            cpasync16(sb + SM_W2BUF + i * 16, srch + i * 16);
            cpasync16(sb + SM_W2BUF + 16384 + i * 16, srcl + i * 16);
        }
        CP_COMMIT();
    }

    // ---- epilogue 1: relu(acc1 + b1) -> bf16 hi/lo into A2 images ----
    {
        const float* b1s = fsm + SM_B1 / 4;
        #pragma unroll
        for (int mt = 0; mt < 2; mt++) {
            const int r0 = Rw + mt * 16 + q;
            #pragma unroll
            for (int nt = 0; nt < 16; nt++) {
                const int c0 = wn * 128 + nt * 8 + s2;
                const int chunk = c0 >> 6, kk = c0 & 63;
                const float bb0 = b1s[c0], bb1 = b1s[c0 + 1];
                float v0 = fmaxf(acc1[mt][nt][0] + bb0, 0.f);
                float v1 = fmaxf(acc1[mt][nt][1] + bb1, 0.f);
                uint32_t hw = cvt2(v1, v0);
                uint32_t lw = cvt2(v1 - __uint_as_float(hw & 0xFFFF0000u),
                                   v0 - __uint_as_float(hw << 16));
                uint32_t off = sw128((uint32_t)(r0 * 128 + kk * 2));
                *(uint32_t*)(sarr + SM_A2H + chunk * 16384 + off) = hw;
                *(uint32_t*)(sarr + SM_A2L + chunk * 16384 + off) = lw;
                float w0 = fmaxf(acc1[mt][nt][2] + bb0, 0.f);
                float w1 = fmaxf(acc1[mt][nt][3] + bb1, 0.f);
                uint32_t hw2 = cvt2(w1, w0);
                uint32_t lw2 = cvt2(w1 - __uint_as_float(hw2 & 0xFFFF0000u),
                                    w0 - __uint_as_float(hw2 << 16));
                uint32_t off2 = sw128((uint32_t)((r0 + 8) * 128 + kk * 2));
                *(uint32_t*)(sarr + SM_A2H + chunk * 16384 + off2) = hw2;
                *(uint32_t*)(sarr + SM_A2L + chunk * 16384 + off2) = lw2;
            }
        }
    }
    __syncthreads();   // A2 images visible

    // ---- layer 2 + 3: 8 stages (2 n-halves x 4 k-chunks), cp.async double buffer ----
    float rowsum[4] = {0.f, 0.f, 0.f, 0.f};
    float acc[2][8][4];

    #pragma unroll 1
    for (int t = 0; t < 8; t++) {
        const int kc = t & 3, buf = t & 1, npass = t >> 2;
        if (t < 7) {
            const int t1 = t + 1;
            const char* srch = (const char*)&g_W2img[0][n][t1 >> 2][t1 & 3][0];
            const char* srcl = (const char*)&g_W2img[1][n][t1 >> 2][t1 & 3][0];
            const uint32_t d = sb + SM_W2BUF + (uint32_t)((t1 & 1) * 32768);
            for (int i = tid; i < 1024; i += 256) {
                cpasync16(d + i * 16, srch + i * 16);
                cpasync16(d + 16384 + i * 16, srcl + i * 16);
            }
            CP_COMMIT();
            CP_WAIT(1);
        } else {
            CP_WAIT(0);
        }
        __syncthreads();

        if (kc == 0) {
            #pragma unroll
            for (int mt = 0; mt < 2; mt++)
                #pragma unroll
                for (int nt = 0; nt < 8; nt++)
                    #pragma unroll
                    for (int e = 0; e < 4; e++) acc[mt][nt][e] = 0.f;
        }

        const uint32_t abh = sb + SM_A2H + (uint32_t)(kc * 16384);
        const uint32_t abl = sb + SM_A2L + (uint32_t)(kc * 16384);
        const uint32_t bb  = sb + SM_W2BUF + (uint32_t)(buf * 32768);

        #pragma unroll
        for (int ks = 0; ks < 4; ks++) {
            const int k = ks * 16;
            uint32_t ah[2][4], al[2][4];
            #pragma unroll
            for (int mt = 0; mt < 2; mt++) {
                uint32_t o = sw128((uint32_t)((Rw + mt * 16 + aRow) * 128 + (k + aCol) * 2));
                ldm4(ah[mt], abh + o);
                ldm4(al[mt], abl + o);
            }
            #pragma unroll
            for (int pair = 0; pair < 4; pair++) {
                const int n0 = wn * 64 + pair * 16;
                uint32_t ob = sw128((uint32_t)((n0 + bRow) * 128 + (k + bCol) * 2));
                uint32_t bh[4], bl[4];
                ldm4(bh, bb + ob);
                ldm4(bl, bb + 16384u + ob);
                #pragma unroll
                for (int mt = 0; mt < 2; mt++)
                    #pragma unroll
                    for (int sub = 0; sub < 2; sub++) {
                        const int nt = pair * 2 + sub;
                        mma16816(acc[mt][nt], ah[mt], bh[sub * 2], bh[sub * 2 + 1]);
                        mma16816(acc[mt][nt], ah[mt], bl[sub * 2], bl[sub * 2 + 1]);
                        mma16816(acc[mt][nt], al[mt], bh[sub * 2], bh[sub * 2 + 1]);
                    }
            }
        }

        if (kc == 3) {
            // fold layer-3: relu(acc + b2) . W3 into per-row partial sums
            const float* b2s = fsm + SM_B2 / 4;
            const float* w3s = fsm + SM_W3 / 4;
            #pragma unroll
            for (int mt = 0; mt < 2; mt++)
                #pragma unroll
                for (int nt = 0; nt < 8; nt++) {
                    const int c0 = npass * 128 + wn * 64 + nt * 8 + s2;
                    const float bb0 = b2s[c0], bb1 = b2s[c0 + 1];
                    const float u0 = w3s[c0], u1 = w3s[c0 + 1];
                    rowsum[mt * 2 + 0] += fmaxf(acc[mt][nt][0] + bb0, 0.f) * u0
                                        + fmaxf(acc[mt][nt][1] + bb1, 0.f) * u1;
                    rowsum[mt * 2 + 1] += fmaxf(acc[mt][nt][2] + bb0, 0.f) * u0
                                        + fmaxf(acc[mt][nt][3] + bb1, 0.f) * u1;
                }
        }
        __syncthreads();
    }

    // reduce across the 4 lanes sharing each row, then across the 2 n-warps
    #pragma unroll
    for (int i = 0; i < 4; i++) {
        float v = rowsum[i];
        v += __shfl_xor_sync(0xffffffffu, v, 1);
        v += __shfl_xor_sync(0xffffffffu, v, 2);
        rowsum[i] = v;
    }
    if ((lane & 3) == 0) {
        #pragma unroll
        for (int i = 0; i < 4; i++) {
            const int row = Rw + (i >> 1) * 16 + (i & 1) * 8 + q;
            fsm[SM_RED / 4 + wn * 128 + row] = rowsum[i];
        }
    }
    __syncthreads();
    if (tid < 128)
        out[n * BSZ + tile * 128 + tid] =
            fsm[SM_RED / 4 + tid] + fsm[SM_RED / 4 + 128 + tid] + b3[n];
}

extern "C" void kernel_launch(void* const* d_in, const int* in_sizes, int n_in,
                              void* d_out, int out_size)
{
    const float* state  = (const float*)d_in[0];
    const float* action = (const float*)d_in[1];
    const float* W1     = (const float*)d_in[2];
    const float* b1     = (const float*)d_in[3];
    const float* W2     = (const float*)d_in[4];
    const float* b2     = (const float*)d_in[5];
    const float* W3     = (const float*)d_in[6];
    const float* b3     = (const float*)d_in[7];
    float* out = (float*)d_out;

    prep_x_kernel<<<NTILES, 256>>>(state, action);
    prep_w1_kernel<<<NQ, 256>>>(W1);
    prep_w2_kernel<<<NQ * 4, 256>>>(W2);

    cudaFuncSetAttribute(qens_hmma_kernel,
                         cudaFuncAttributeMaxDynamicSharedMemorySize, SM_TOTAL);
    dim3 grid(NTILES, NQ);
    qens_hmma_kernel<<<grid, 256, SM_TOTAL>>>(b1, b2, W3, b3, out);
}

// round 5
// speedup vs baseline: 2.5708x; 1.0327x over previous
#include <cuda_runtime.h>
#include <cuda_bf16.h>
#include <stdint.h>

#define NQ     10
#define BSZ    32768
#define NTILES 512            // 64-row batch tiles

// Pre-split (hi/lo bf16), pre-SW128-swizzled images.
__device__ __nv_bfloat16 g_Ximg[2][NTILES][4096];      // [split][tile][64 rows x 64 k]
__device__ __nv_bfloat16 g_W1img[2][NQ][16384];        // [split][net][256 feat x 64 k]
__device__ __nv_bfloat16 g_W2img[2][NQ][2][4][8192];   // [split][net][nhalf][kc][128 n x 64 k]

__device__ __forceinline__ uint32_t smem_u32(const void* p) {
    uint32_t a;
    asm("{ .reg .u64 t; cvta.to.shared.u64 t, %1; cvt.u32.u64 %0, t; }" : "=r"(a) : "l"(p));
    return a;
}
__device__ __forceinline__ uint32_t sw128(uint32_t off) { return off ^ ((off >> 3) & 0x70); }
__device__ __forceinline__ uint32_t cvt2(float hi, float lo) {
    uint32_t r;
    asm("cvt.rn.bf16x2.f32 %0, %1, %2;" : "=r"(r) : "f"(hi), "f"(lo));
    return r;
}
__device__ __forceinline__ void cpasync16(uint32_t dst, const void* src) {
    asm volatile("cp.async.cg.shared.global [%0], [%1], 16;" :: "r"(dst), "l"(src) : "memory");
}
#define CP_COMMIT() asm volatile("cp.async.commit_group;" ::: "memory")
#define CP_WAIT(n)  asm volatile("cp.async.wait_group %0;" :: "n"(n) : "memory")

__device__ __forceinline__ void ldm4(uint32_t r[4], uint32_t addr) {
    asm volatile("ldmatrix.sync.aligned.m8n8.x4.shared.b16 {%0,%1,%2,%3}, [%4];"
        : "=r"(r[0]), "=r"(r[1]), "=r"(r[2]), "=r"(r[3]) : "r"(addr));
}
__device__ __forceinline__ void mma16816(float c[4], const uint32_t a[4],
                                         uint32_t b0, uint32_t b1) {
    asm volatile("mma.sync.aligned.m16n8k16.row.col.f32.bf16.bf16.f32 "
        "{%0,%1,%2,%3}, {%4,%5,%6,%7}, {%8,%9}, {%0,%1,%2,%3};"
        : "+f"(c[0]), "+f"(c[1]), "+f"(c[2]), "+f"(c[3])
        : "r"(a[0]), "r"(a[1]), "r"(a[2]), "r"(a[3]), "r"(b0), "r"(b1));
}

// split a value pair into hi / lo bf16x2 words
__device__ __forceinline__ void split2(float v0, float v1, uint32_t& hw, uint32_t& lw) {
    hw = cvt2(v1, v0);
    lw = cvt2(v1 - __uint_as_float(hw & 0xFFFF0000u),
              v0 - __uint_as_float(hw << 16));
}

// ============================ prep kernels (direct swizzled stores) ============================
__global__ void __launch_bounds__(256) prep_x_kernel(const float* __restrict__ state,
                                                     const float* __restrict__ action) {
    const int t = blockIdx.x;                    // 512 tiles x 64 rows
    char* dh = (char*)&g_Ximg[0][t][0];
    char* dl = (char*)&g_Ximg[1][t][0];
    for (int idx = threadIdx.x; idx < 64 * 32; idx += 256) {
        int r = idx >> 5, k2 = idx & 31;
        int R = t * 64 + r, k = k2 * 2;
        float v0 = 0.f, v1 = 0.f;
        if (k < 17)       v0 = state[R * 17 + k];
        else if (k < 23)  v0 = action[R * 6 + (k - 17)];
        if (k + 1 < 17)      v1 = state[R * 17 + k + 1];
        else if (k + 1 < 23) v1 = action[R * 6 + (k + 1 - 17)];
        uint32_t hw, lw; split2(v0, v1, hw, lw);
        uint32_t off = sw128((uint32_t)(r * 128 + k2 * 4));
        *(uint32_t*)(dh + off) = hw;
        *(uint32_t*)(dl + off) = lw;
    }
}

__global__ void __launch_bounds__(256) prep_w1_kernel(const float* __restrict__ W1) {
    const int n = blockIdx.x >> 2, qtr = blockIdx.x & 3;   // 40 blocks
    char* dh = (char*)&g_W1img[0][n][0];
    char* dl = (char*)&g_W1img[1][n][0];
    for (int idx = threadIdx.x; idx < 64 * 32; idx += 256) {
        int rl = idx >> 5, k2 = idx & 31;
        int r = qtr * 64 + rl, k = k2 * 2;      // r = out feature, k = in dim
        float v0 = (k     < 23) ? W1[(n * 23 + k)     * 256 + r] : 0.f;
        float v1 = (k + 1 < 23) ? W1[(n * 23 + k + 1) * 256 + r] : 0.f;
        uint32_t hw, lw; split2(v0, v1, hw, lw);
        uint32_t off = sw128((uint32_t)(r * 128 + k2 * 4));
        *(uint32_t*)(dh + off) = hw;
        *(uint32_t*)(dl + off) = lw;
    }
}

__global__ void __launch_bounds__(256) prep_w2_kernel(const float* __restrict__ W2) {
    const int n = blockIdx.x >> 3, rest = blockIdx.x & 7;  // 80 blocks
    const int nhalf = rest >> 2, kc = rest & 3;
    char* dh = (char*)&g_W2img[0][n][nhalf][kc][0];
    char* dl = (char*)&g_W2img[1][n][nhalf][kc][0];
    const float* src = W2 + n * 65536;
    for (int idx = threadIdx.x; idx < 128 * 32; idx += 256) {
        int nl = idx >> 5, k2 = idx & 31;
        int kg = kc * 64 + k2 * 2, ng = nhalf * 128 + nl;
        float v0 = src[kg * 256 + ng];
        float v1 = src[(kg + 1) * 256 + ng];
        uint32_t hw, lw; split2(v0, v1, hw, lw);
        uint32_t off = sw128((uint32_t)(nl * 128 + k2 * 4));
        *(uint32_t*)(dh + off) = hw;
        *(uint32_t*)(dl + off) = lw;
    }
}

// ============================ main fused kernel (M=64, 2 CTAs/SM) ============================
// Phase-2 SMEM: A2H [4 x 8KB] @0, A2L @32768, W2 ring 2x16KB @65536, misc @98304.
// Phase-1 overlay: W1h @0 (32KB), W1l @32768 (32KB), Xh @65536 (8KB), Xl @73728 (8KB).
#define SM_A2H   0
#define SM_W1H   0
#define SM_A2L   32768
#define SM_W1L   32768
#define SM_W2BUF 65536
#define SM_XH    65536
#define SM_XL    73728
#define SM_B1    98304
#define SM_B2    99328
#define SM_W3    100352
#define SM_RED   101376      // 4 n-warps x 64 rows x f32
#define SM_TOTAL 102400

__global__ void __launch_bounds__(256, 2)
qens_hmma_kernel(const float* __restrict__ b1, const float* __restrict__ b2,
                 const float* __restrict__ W3, const float* __restrict__ b3,
                 float* __restrict__ out) {
    extern __shared__ char sarr[];
    float* fsm = (float*)sarr;
    const uint32_t sb = smem_u32(sarr);
    const int tid  = threadIdx.x;
    const int wid  = tid >> 5;
    const int lane = tid & 31;
    const int tile = blockIdx.x;
    const int n    = blockIdx.y;

    const int wm = wid & 1, wn = wid >> 1;     // 2 m-warps x 4 n-warps
    const int Rw = wm * 32;
    const int aRow = (lane & 7) + ((lane >> 3) & 1) * 8;
    const int aCol = (lane >> 4) * 8;
    const int bRow = (lane & 7) + ((lane >> 4) << 3);
    const int bCol = ((lane >> 3) & 1) * 8;
    const int q  = lane >> 2;
    const int s2 = (lane & 3) * 2;

    // ---- stage phase-1 operands via cp.async ----
    {
        const char* xh = (const char*)&g_Ximg[0][tile][0];
        const char* xl = (const char*)&g_Ximg[1][tile][0];
        for (int i = tid; i < 512; i += 256) {
            cpasync16(sb + SM_XH + i * 16, xh + i * 16);
            cpasync16(sb + SM_XL + i * 16, xl + i * 16);
        }
        const char* w1h = (const char*)&g_W1img[0][n][0];
        const char* w1l = (const char*)&g_W1img[1][n][0];
        for (int i = tid; i < 2048; i += 256) {
            cpasync16(sb + SM_W1H + i * 16, w1h + i * 16);
            cpasync16(sb + SM_W1L + i * 16, w1l + i * 16);
        }
        CP_COMMIT();
    }
    fsm[SM_B1 / 4 + tid] = b1[n * 256 + tid];
    fsm[SM_B2 / 4 + tid] = b2[n * 256 + tid];
    fsm[SM_W3 / 4 + tid] = W3[n * 256 + tid];
    CP_WAIT(0);
    __syncthreads();

    // ---- layer 1: warp tile 32 rows x 64 cols, 3-term bf16 split ----
    float acc1[2][8][4];
    #pragma unroll
    for (int mt = 0; mt < 2; mt++)
        #pragma unroll
        for (int nt = 0; nt < 8; nt++)
            #pragma unroll
            for (int e = 0; e < 4; e++) acc1[mt][nt][e] = 0.f;

    #pragma unroll
    for (int ks = 0; ks < 2; ks++) {
        const int k = ks * 16;
        uint32_t ah[2][4], al[2][4];
        #pragma unroll
        for (int mt = 0; mt < 2; mt++) {
            uint32_t o = sw128((uint32_t)((Rw + mt * 16 + aRow) * 128 + (k + aCol) * 2));
            ldm4(ah[mt], sb + SM_XH + o);
            ldm4(al[mt], sb + SM_XL + o);
        }
        #pragma unroll
        for (int pair = 0; pair < 4; pair++) {
            const int n0 = wn * 64 + pair * 16;
            uint32_t ob = sw128((uint32_t)((n0 + bRow) * 128 + (k + bCol) * 2));
            uint32_t bh[4], bl[4];
            ldm4(bh, sb + SM_W1H + ob);
            ldm4(bl, sb + SM_W1L + ob);
            #pragma unroll
            for (int mt = 0; mt < 2; mt++)
                #pragma unroll
                for (int sub = 0; sub < 2; sub++) {
                    const int nt = pair * 2 + sub;
                    mma16816(acc1[mt][nt], ah[mt], bh[sub * 2], bh[sub * 2 + 1]);
                    mma16816(acc1[mt][nt], ah[mt], bl[sub * 2], bl[sub * 2 + 1]);
                    mma16816(acc1[mt][nt], al[mt], bh[sub * 2], bh[sub * 2 + 1]);
                }
        }
    }
    __syncthreads();   // X / W1 regions free

    // prefetch W2 stage 0 into ring buf0 while epilogue-1 runs
    {
        const char* src = (const char*)&g_W2img[0][n][0][0][0];
        for (int i = tid; i < 1024; i += 256)
            cpasync16(sb + SM_W2BUF + i * 16, src + i * 16);
        CP_COMMIT();
    }

    // ---- epilogue 1: relu(acc1 + b1) -> bf16 hi/lo into A2 images (chunk == wn) ----
    {
        const float* b1s = fsm + SM_B1 / 4;
        const uint32_t baseH = sb + SM_A2H + (uint32_t)(wn * 8192);
        const uint32_t baseL = sb + SM_A2L + (uint32_t)(wn * 8192);
        #pragma unroll
        for (int mt = 0; mt < 2; mt++) {
            const int r0 = Rw + mt * 16 + q;
            #pragma unroll
            for (int nt = 0; nt < 8; nt++) {
                const int c0 = wn * 64 + nt * 8 + s2;
                const int kk = c0 & 63;
                const float bb0 = b1s[c0], bb1 = b1s[c0 + 1];
                uint32_t hw, lw;
                split2(fmaxf(acc1[mt][nt][0] + bb0, 0.f),
                       fmaxf(acc1[mt][nt][1] + bb1, 0.f), hw, lw);
                uint32_t off = sw128((uint32_t)(r0 * 128 + kk * 2));
                *(uint32_t*)(sarr + (baseH - sb) + off) = hw;
                *(uint32_t*)(sarr + (baseL - sb) + off) = lw;
                uint32_t hw2, lw2;
                split2(fmaxf(acc1[mt][nt][2] + bb0, 0.f),
                       fmaxf(acc1[mt][nt][3] + bb1, 0.f), hw2, lw2);
                uint32_t off2 = sw128((uint32_t)((r0 + 8) * 128 + kk * 2));
                *(uint32_t*)(sarr + (baseH - sb) + off2) = hw2;
                *(uint32_t*)(sarr + (baseL - sb) + off2) = lw2;
            }
        }
    }
    __syncthreads();   // A2 images visible

    // ---- layer 2 + 3: 16 stages (2 npass x 4 kc x 2 split), 16KB ring x2 ----
    float rowsum[4] = {0.f, 0.f, 0.f, 0.f};
    float acc[2][4][4];

    #pragma unroll 1
    for (int t = 0; t < 16; t++) {
        const int npass = t >> 3, kc = (t >> 1) & 3, split = t & 1, buf = t & 1;
        if (t < 15) {
            const int t1 = t + 1;
            const char* src = (const char*)&g_W2img[t1 & 1][n][t1 >> 3][(t1 >> 1) & 3][0];
            const uint32_t d = sb + SM_W2BUF + (uint32_t)(((t1) & 1) * 16384);
            for (int i = tid; i < 1024; i += 256)
                cpasync16(d + i * 16, src + i * 16);
            CP_COMMIT();
            CP_WAIT(1);
        } else {
            CP_WAIT(0);
        }
        __syncthreads();

        if ((t & 7) == 0) {
            #pragma unroll
            for (int mt = 0; mt < 2; mt++)
                #pragma unroll
                for (int nt = 0; nt < 4; nt++)
                    #pragma unroll
                    for (int e = 0; e < 4; e++) acc[mt][nt][e] = 0.f;
        }

        const uint32_t abh = sb + SM_A2H + (uint32_t)(kc * 8192);
        const uint32_t abl = sb + SM_A2L + (uint32_t)(kc * 8192);
        const uint32_t bb  = sb + SM_W2BUF + (uint32_t)(buf * 16384);

        if (split == 0) {
            #pragma unroll
            for (int ks = 0; ks < 4; ks++) {
                const int k = ks * 16;
                uint32_t ah[2][4], al[2][4];
                #pragma unroll
                for (int mt = 0; mt < 2; mt++) {
                    uint32_t o = sw128((uint32_t)((Rw + mt * 16 + aRow) * 128 + (k + aCol) * 2));
                    ldm4(ah[mt], abh + o);
                    ldm4(al[mt], abl + o);
                }
                #pragma unroll
                for (int pair = 0; pair < 2; pair++) {
                    const int n0 = wn * 32 + pair * 16;
                    uint32_t ob = sw128((uint32_t)((n0 + bRow) * 128 + (k + bCol) * 2));
                    uint32_t bf[4];
                    ldm4(bf, bb + ob);
                    #pragma unroll
                    for (int mt = 0; mt < 2; mt++)
                        #pragma unroll
                        for (int sub = 0; sub < 2; sub++) {
                            const int nt = pair * 2 + sub;
                            mma16816(acc[mt][nt], ah[mt], bf[sub * 2], bf[sub * 2 + 1]);
                            mma16816(acc[mt][nt], al[mt], bf[sub * 2], bf[sub * 2 + 1]);
                        }
                }
            }
        } else {
            #pragma unroll
            for (int ks = 0; ks < 4; ks++) {
                const int k = ks * 16;
                uint32_t ah[2][4];
                #pragma unroll
                for (int mt = 0; mt < 2; mt++) {
                    uint32_t o = sw128((uint32_t)((Rw + mt * 16 + aRow) * 128 + (k + aCol) * 2));
                    ldm4(ah[mt], abh + o);
                }
                #pragma unroll
                for (int pair = 0; pair < 2; pair++) {
                    const int n0 = wn * 32 + pair * 16;
                    uint32_t ob = sw128((uint32_t)((n0 + bRow) * 128 + (k + bCol) * 2));
                    uint32_t bf[4];
                    ldm4(bf, bb + ob);
                    #pragma unroll
                    for (int mt = 0; mt < 2; mt++)
                        #pragma unroll
                        for (int sub = 0; sub < 2; sub++) {
                            const int nt = pair * 2 + sub;
                            mma16816(acc[mt][nt], ah[mt], bf[sub * 2], bf[sub * 2 + 1]);
                        }
                }
            }
        }

        if ((t & 7) == 7) {
            const float* b2s = fsm + SM_B2 / 4;
            const float* w3s = fsm + SM_W3 / 4;
            #pragma unroll
            for (int mt = 0; mt < 2; mt++)
                #pragma unroll
                for (int nt = 0; nt < 4; nt++) {
                    const int c0 = npass * 128 + wn * 32 + nt * 8 + s2;
                    const float bb0 = b2s[c0], bb1 = b2s[c0 + 1];
                    const float u0 = w3s[c0], u1 = w3s[c0 + 1];
                    rowsum[mt * 2 + 0] += fmaxf(acc[mt][nt][0] + bb0, 0.f) * u0
                                        + fmaxf(acc[mt][nt][1] + bb1, 0.f) * u1;
                    rowsum[mt * 2 + 1] += fmaxf(acc[mt][nt][2] + bb0, 0.f) * u0
                                        + fmaxf(acc[mt][nt][3] + bb1, 0.f) * u1;
                }
        }
        __syncthreads();
    }

    // reduce over the 4 col-lanes per row, then across the 4 n-warps
    #pragma unroll
    for (int i = 0; i < 4; i++) {
        float v = rowsum[i];
        v += __shfl_xor_sync(0xffffffffu, v, 1);
        v += __shfl_xor_sync(0xffffffffu, v, 2);
        rowsum[i] = v;
    }
    if ((lane & 3) == 0) {
        #pragma unroll
        for (int i = 0; i < 4; i++) {
            const int row = Rw + (i >> 1) * 16 + (i & 1) * 8 + q;
            fsm[SM_RED / 4 + wn * 64 + row] = rowsum[i];
        }
    }
    __syncthreads();
    if (tid < 64) {
        const float* red = fsm + SM_RED / 4;
        out[n * BSZ + tile * 64 + tid] =
            red[tid] + red[64 + tid] + red[128 + tid] + red[192 + tid] + b3[n];
    }
}

extern "C" void kernel_launch(void* const* d_in, const int* in_sizes, int n_in,
                              void* d_out, int out_size)
{
    const float* state  = (const float*)d_in[0];
    const float* action = (const float*)d_in[1];
    const float* W1     = (const float*)d_in[2];
    const float* b1     = (const float*)d_in[3];
    const float* W2     = (const float*)d_in[4];
    const float* b2     = (const float*)d_in[5];
    const float* W3     = (const float*)d_in[6];
    const float* b3     = (const float*)d_in[7];
    float* out = (float*)d_out;

    prep_x_kernel<<<NTILES, 256>>>(state, action);
    prep_w1_kernel<<<NQ * 4, 256>>>(W1);
    prep_w2_kernel<<<NQ * 8, 256>>>(W2);

    cudaFuncSetAttribute(qens_hmma_kernel,
                         cudaFuncAttributeMaxDynamicSharedMemorySize, SM_TOTAL);
    dim3 grid(NTILES, NQ);
    qens_hmma_kernel<<<grid, 256, SM_TOTAL>>>(b1, b2, W3, b3, out);
}

// round 6
// speedup vs baseline: 2.5710x; 1.0001x over previous
#include <cuda_runtime.h>
#include <cuda_bf16.h>
#include <stdint.h>

#define NQ     10
#define BSZ    32768
#define NTILES 512            // 64-row batch tiles

// Pre-split (hi/lo bf16), pre-SW128-swizzled images.
__device__ __nv_bfloat16 g_Ximg[2][NTILES][4096];      // [split][tile][64 rows x 64 k]
__device__ __nv_bfloat16 g_W1img[2][NQ][16384];        // [split][net][256 feat x 64 k]
__device__ __nv_bfloat16 g_W2img[2][NQ][2][4][8192];   // [split][net][nhalf][kc][128 n x 64 k]

__device__ __forceinline__ uint32_t smem_u32(const void* p) {
    uint32_t a;
    asm("{ .reg .u64 t; cvta.to.shared.u64 t, %1; cvt.u32.u64 %0, t; }" : "=r"(a) : "l"(p));
    return a;
}
__device__ __forceinline__ uint32_t sw128(uint32_t off) { return off ^ ((off >> 3) & 0x70); }
__device__ __forceinline__ uint32_t cvt2(float hi, float lo) {
    uint32_t r;
    asm("cvt.rn.bf16x2.f32 %0, %1, %2;" : "=r"(r) : "f"(hi), "f"(lo));
    return r;
}
__device__ __forceinline__ void cpasync16(uint32_t dst, const void* src) {
    asm volatile("cp.async.cg.shared.global [%0], [%1], 16;" :: "r"(dst), "l"(src) : "memory");
}
#define CP_COMMIT() asm volatile("cp.async.commit_group;" ::: "memory")
#define CP_WAIT(n)  asm volatile("cp.async.wait_group %0;" :: "n"(n) : "memory")

__device__ __forceinline__ void ldm4(uint32_t r[4], uint32_t addr) {
    asm volatile("ldmatrix.sync.aligned.m8n8.x4.shared.b16 {%0,%1,%2,%3}, [%4];"
        : "=r"(r[0]), "=r"(r[1]), "=r"(r[2]), "=r"(r[3]) : "r"(addr));
}
__device__ __forceinline__ void mma16816(float c[4], const uint32_t a[4],
                                         uint32_t b0, uint32_t b1) {
    asm volatile("mma.sync.aligned.m16n8k16.row.col.f32.bf16.bf16.f32 "
        "{%0,%1,%2,%3}, {%4,%5,%6,%7}, {%8,%9}, {%0,%1,%2,%3};"
        : "+f"(c[0]), "+f"(c[1]), "+f"(c[2]), "+f"(c[3])
        : "r"(a[0]), "r"(a[1]), "r"(a[2]), "r"(a[3]), "r"(b0), "r"(b1));
}

// split a value pair into hi / lo bf16x2 words
__device__ __forceinline__ void split2(float v0, float v1, uint32_t& hw, uint32_t& lw) {
    hw = cvt2(v1, v0);
    lw = cvt2(v1 - __uint_as_float(hw & 0xFFFF0000u),
              v0 - __uint_as_float(hw << 16));
}

// ============================ prep kernels (direct swizzled stores) ============================
__global__ void __launch_bounds__(256) prep_x_kernel(const float* __restrict__ state,
                                                     const float* __restrict__ action) {
    const int t = blockIdx.x;                    // 512 tiles x 64 rows
    char* dh = (char*)&g_Ximg[0][t][0];
    char* dl = (char*)&g_Ximg[1][t][0];
    for (int idx = threadIdx.x; idx < 64 * 32; idx += 256) {
        int r = idx >> 5, k2 = idx & 31;
        int R = t * 64 + r, k = k2 * 2;
        float v0 = 0.f, v1 = 0.f;
        if (k < 17)       v0 = state[R * 17 + k];
        else if (k < 23)  v0 = action[R * 6 + (k - 17)];
        if (k + 1 < 17)      v1 = state[R * 17 + k + 1];
        else if (k + 1 < 23) v1 = action[R * 6 + (k + 1 - 17)];
        uint32_t hw, lw; split2(v0, v1, hw, lw);
        uint32_t off = sw128((uint32_t)(r * 128 + k2 * 4));
        *(uint32_t*)(dh + off) = hw;
        *(uint32_t*)(dl + off) = lw;
    }
}

__global__ void __launch_bounds__(256) prep_w1_kernel(const float* __restrict__ W1) {
    const int n = blockIdx.x >> 2, qtr = blockIdx.x & 3;   // 40 blocks
    char* dh = (char*)&g_W1img[0][n][0];
    char* dl = (char*)&g_W1img[1][n][0];
    for (int idx = threadIdx.x; idx < 64 * 32; idx += 256) {
        int rl = idx >> 5, k2 = idx & 31;
        int r = qtr * 64 + rl, k = k2 * 2;      // r = out feature, k = in dim
        float v0 = (k     < 23) ? W1[(n * 23 + k)     * 256 + r] : 0.f;
        float v1 = (k + 1 < 23) ? W1[(n * 23 + k + 1) * 256 + r] : 0.f;
        uint32_t hw, lw; split2(v0, v1, hw, lw);
        uint32_t off = sw128((uint32_t)(r * 128 + k2 * 4));
        *(uint32_t*)(dh + off) = hw;
        *(uint32_t*)(dl + off) = lw;
    }
}

__global__ void __launch_bounds__(256) prep_w2_kernel(const float* __restrict__ W2) {
    const int n = blockIdx.x >> 3, rest = blockIdx.x & 7;  // 80 blocks
    const int nhalf = rest >> 2, kc = rest & 3;
    char* dh = (char*)&g_W2img[0][n][nhalf][kc][0];
    char* dl = (char*)&g_W2img[1][n][nhalf][kc][0];
    const float* src = W2 + n * 65536;
    for (int idx = threadIdx.x; idx < 128 * 32; idx += 256) {
        int nl = idx >> 5, k2 = idx & 31;
        int kg = kc * 64 + k2 * 2, ng = nhalf * 128 + nl;
        float v0 = src[kg * 256 + ng];
        float v1 = src[(kg + 1) * 256 + ng];
        uint32_t hw, lw; split2(v0, v1, hw, lw);
        uint32_t off = sw128((uint32_t)(nl * 128 + k2 * 4));
        *(uint32_t*)(dh + off) = hw;
        *(uint32_t*)(dl + off) = lw;
    }
}

// ============================ main fused kernel (M=64, 2 CTAs/SM) ============================
// Phase-2 SMEM: A2H [4 x 8KB] @0, A2L @32768, W2 ring 2x16KB @65536, misc @98304.
// Phase-1 overlay: W1h @0 (32KB), W1l @32768 (32KB), Xh @65536 (8KB), Xl @73728 (8KB).
#define SM_A2H   0
#define SM_W1H   0
#define SM_A2L   32768
#define SM_W1L   32768
#define SM_W2BUF 65536
#define SM_XH    65536
#define SM_XL    73728
#define SM_B1    98304
#define SM_B2    99328
#define SM_W3    100352
#define SM_RED   101376      // 4 n-warps x 64 rows x f32
#define SM_TOTAL 102400

__global__ void __launch_bounds__(256, 2)
qens_hmma_kernel(const float* __restrict__ b1, const float* __restrict__ b2,
                 const float* __restrict__ W3, const float* __restrict__ b3,
                 float* __restrict__ out) {
    extern __shared__ char sarr[];
    float* fsm = (float*)sarr;
    const uint32_t sb = smem_u32(sarr);
    const int tid  = threadIdx.x;
    const int wid  = tid >> 5;
    const int lane = tid & 31;
    const int tile = blockIdx.x;
    const int n    = blockIdx.y;

    const int wm = wid & 1, wn = wid >> 1;     // 2 m-warps x 4 n-warps
    const int Rw = wm * 32;
    const int aRow = (lane & 7) + ((lane >> 3) & 1) * 8;
    const int aCol = (lane >> 4) * 8;
    const int bRow = (lane & 7) + ((lane >> 4) << 3);
    const int bCol = ((lane >> 3) & 1) * 8;
    const int q  = lane >> 2;
    const int s2 = (lane & 3) * 2;

    // ---- stage phase-1 operands via cp.async ----
    {
        const char* xh = (const char*)&g_Ximg[0][tile][0];
        const char* xl = (const char*)&g_Ximg[1][tile][0];
        for (int i = tid; i < 512; i += 256) {
            cpasync16(sb + SM_XH + i * 16, xh + i * 16);
            cpasync16(sb + SM_XL + i * 16, xl + i * 16);
        }
        const char* w1h = (const char*)&g_W1img[0][n][0];
        const char* w1l = (const char*)&g_W1img[1][n][0];
        for (int i = tid; i < 2048; i += 256) {
            cpasync16(sb + SM_W1H + i * 16, w1h + i * 16);
            cpasync16(sb + SM_W1L + i * 16, w1l + i * 16);
        }
        CP_COMMIT();
    }
    fsm[SM_B1 / 4 + tid] = b1[n * 256 + tid];
    fsm[SM_B2 / 4 + tid] = b2[n * 256 + tid];
    fsm[SM_W3 / 4 + tid] = W3[n * 256 + tid];
    CP_WAIT(0);
    __syncthreads();

    // ---- layer 1: warp tile 32 rows x 64 cols, 3-term bf16 split ----
    float acc1[2][8][4];
    #pragma unroll
    for (int mt = 0; mt < 2; mt++)
        #pragma unroll
        for (int nt = 0; nt < 8; nt++)
            #pragma unroll
            for (int e = 0; e < 4; e++) acc1[mt][nt][e] = 0.f;

    #pragma unroll
    for (int ks = 0; ks < 2; ks++) {
        const int k = ks * 16;
        uint32_t ah[2][4], al[2][4];
        #pragma unroll
        for (int mt = 0; mt < 2; mt++) {
            uint32_t o = sw128((uint32_t)((Rw + mt * 16 + aRow) * 128 + (k + aCol) * 2));
            ldm4(ah[mt], sb + SM_XH + o);
            ldm4(al[mt], sb + SM_XL + o);
        }
        #pragma unroll
        for (int pair = 0; pair < 4; pair++) {
            const int n0 = wn * 64 + pair * 16;
            uint32_t ob = sw128((uint32_t)((n0 + bRow) * 128 + (k + bCol) * 2));
            uint32_t bh[4], bl[4];
            ldm4(bh, sb + SM_W1H + ob);
            ldm4(bl, sb + SM_W1L + ob);
            #pragma unroll
            for (int mt = 0; mt < 2; mt++)
                #pragma unroll
                for (int sub = 0; sub < 2; sub++) {
                    const int nt = pair * 2 + sub;
                    mma16816(acc1[mt][nt], ah[mt], bh[sub * 2], bh[sub * 2 + 1]);
                    mma16816(acc1[mt][nt], ah[mt], bl[sub * 2], bl[sub * 2 + 1]);
                    mma16816(acc1[mt][nt], al[mt], bh[sub * 2], bh[sub * 2 + 1]);
                }
        }
    }
    __syncthreads();   // X / W1 regions free

    // prefetch W2 stage 0 into ring buf0 while epilogue-1 runs
    {
        const char* src = (const char*)&g_W2img[0][n][0][0][0];
        for (int i = tid; i < 1024; i += 256)
            cpasync16(sb + SM_W2BUF + i * 16, src + i * 16);
        CP_COMMIT();
    }

    // ---- epilogue 1: relu(acc1 + b1) -> bf16 hi/lo into A2 images (chunk == wn) ----
    {
        const float* b1s = fsm + SM_B1 / 4;
        const uint32_t baseH = sb + SM_A2H + (uint32_t)(wn * 8192);
        const uint32_t baseL = sb + SM_A2L + (uint32_t)(wn * 8192);
        #pragma unroll
        for (int mt = 0; mt < 2; mt++) {
            const int r0 = Rw + mt * 16 + q;
            #pragma unroll
            for (int nt = 0; nt < 8; nt++) {
                const int c0 = wn * 64 + nt * 8 + s2;
                const int kk = c0 & 63;
                const float bb0 = b1s[c0], bb1 = b1s[c0 + 1];
                uint32_t hw, lw;
                split2(fmaxf(acc1[mt][nt][0] + bb0, 0.f),
                       fmaxf(acc1[mt][nt][1] + bb1, 0.f), hw, lw);
                uint32_t off = sw128((uint32_t)(r0 * 128 + kk * 2));
                *(uint32_t*)(sarr + (baseH - sb) + off) = hw;
                *(uint32_t*)(sarr + (baseL - sb) + off) = lw;
                uint32_t hw2, lw2;
                split2(fmaxf(acc1[mt][nt][2] + bb0, 0.f),
                       fmaxf(acc1[mt][nt][3] + bb1, 0.f), hw2, lw2);
                uint32_t off2 = sw128((uint32_t)((r0 + 8) * 128 + kk * 2));
                *(uint32_t*)(sarr + (baseH - sb) + off2) = hw2;
                *(uint32_t*)(sarr + (baseL - sb) + off2) = lw2;
            }
        }
    }
    __syncthreads();   // A2 images visible

    // ---- layer 2 + 3: 16 stages (2 npass x 4 kc x 2 split), 16KB ring x2 ----
    float rowsum[4] = {0.f, 0.f, 0.f, 0.f};
    float acc[2][4][4];

    #pragma unroll 1
    for (int t = 0; t < 16; t++) {
        const int npass = t >> 3, kc = (t >> 1) & 3, split = t & 1, buf = t & 1;
        if (t < 15) {
            const int t1 = t + 1;
            const char* src = (const char*)&g_W2img[t1 & 1][n][t1 >> 3][(t1 >> 1) & 3][0];
            const uint32_t d = sb + SM_W2BUF + (uint32_t)(((t1) & 1) * 16384);
            for (int i = tid; i < 1024; i += 256)
                cpasync16(d + i * 16, src + i * 16);
            CP_COMMIT();
            CP_WAIT(1);
        } else {
            CP_WAIT(0);
        }
        __syncthreads();

        if ((t & 7) == 0) {
            #pragma unroll
            for (int mt = 0; mt < 2; mt++)
                #pragma unroll
                for (int nt = 0; nt < 4; nt++)
                    #pragma unroll
                    for (int e = 0; e < 4; e++) acc[mt][nt][e] = 0.f;
        }

        const uint32_t abh = sb + SM_A2H + (uint32_t)(kc * 8192);
        const uint32_t abl = sb + SM_A2L + (uint32_t)(kc * 8192);
        const uint32_t bb  = sb + SM_W2BUF + (uint32_t)(buf * 16384);

        if (split == 0) {
            #pragma unroll
            for (int ks = 0; ks < 4; ks++) {
                const int k = ks * 16;
                uint32_t ah[2][4], al[2][4];
                #pragma unroll
                for (int mt = 0; mt < 2; mt++) {
                    uint32_t o = sw128((uint32_t)((Rw + mt * 16 + aRow) * 128 + (k + aCol) * 2));
                    ldm4(ah[mt], abh + o);
                    ldm4(al[mt], abl + o);
                }
                #pragma unroll
                for (int pair = 0; pair < 2; pair++) {
                    const int n0 = wn * 32 + pair * 16;
                    uint32_t ob = sw128((uint32_t)((n0 + bRow) * 128 + (k + bCol) * 2));
                    uint32_t bf[4];
                    ldm4(bf, bb + ob);
                    #pragma unroll
                    for (int mt = 0; mt < 2; mt++)
                        #pragma unroll
                        for (int sub = 0; sub < 2; sub++) {
                            const int nt = pair * 2 + sub;
                            mma16816(acc[mt][nt], ah[mt], bf[sub * 2], bf[sub * 2 + 1]);
                            mma16816(acc[mt][nt], al[mt], bf[sub * 2], bf[sub * 2 + 1]);
                        }
                }
            }
        } else {
            #pragma unroll
            for (int ks = 0; ks < 4; ks++) {
                const int k = ks * 16;
                uint32_t ah[2][4];
                #pragma unroll
                for (int mt = 0; mt < 2; mt++) {
                    uint32_t o = sw128((uint32_t)((Rw + mt * 16 + aRow) * 128 + (k + aCol) * 2));
                    ldm4(ah[mt], abh + o);
                }
                #pragma unroll
                for (int pair = 0; pair < 2; pair++) {
                    const int n0 = wn * 32 + pair * 16;
                    uint32_t ob = sw128((uint32_t)((n0 + bRow) * 128 + (k + bCol) * 2));
                    uint32_t bf[4];
                    ldm4(bf, bb + ob);
                    #pragma unroll
                    for (int mt = 0; mt < 2; mt++)
                        #pragma unroll
                        for (int sub = 0; sub < 2; sub++) {
                            const int nt = pair * 2 + sub;
                            mma16816(acc[mt][nt], ah[mt], bf[sub * 2], bf[sub * 2 + 1]);
                        }
                }
            }
        }

        if ((t & 7) == 7) {
            const float* b2s = fsm + SM_B2 / 4;
            const float* w3s = fsm + SM_W3 / 4;
            #pragma unroll
            for (int mt = 0; mt < 2; mt++)
                #pragma unroll
                for (int nt = 0; nt < 4; nt++) {
                    const int c0 = npass * 128 + wn * 32 + nt * 8 + s2;
                    const float bb0 = b2s[c0], bb1 = b2s[c0 + 1];
                    const float u0 = w3s[c0], u1 = w3s[c0 + 1];
                    rowsum[mt * 2 + 0] += fmaxf(acc[mt][nt][0] + bb0, 0.f) * u0
                                        + fmaxf(acc[mt][nt][1] + bb1, 0.f) * u1;
                    rowsum[mt * 2 + 1] += fmaxf(acc[mt][nt][2] + bb0, 0.f) * u0
                                        + fmaxf(acc[mt][nt][3] + bb1, 0.f) * u1;
                }
        }
        __syncthreads();
    }

    // reduce over the 4 col-lanes per row, then across the 4 n-warps
    #pragma unroll
    for (int i = 0; i < 4; i++) {
        float v = rowsum[i];
        v += __shfl_xor_sync(0xffffffffu, v, 1);
        v += __shfl_xor_sync(0xffffffffu, v, 2);
        rowsum[i] = v;
    }
    if ((lane & 3) == 0) {
        #pragma unroll
        for (int i = 0; i < 4; i++) {
            const int row = Rw + (i >> 1) * 16 + (i & 1) * 8 + q;
            fsm[SM_RED / 4 + wn * 64 + row] = rowsum[i];
        }
    }
    __syncthreads();
    if (tid < 64) {
        const float* red = fsm + SM_RED / 4;
        out[n * BSZ + tile * 64 + tid] =
            red[tid] + red[64 + tid] + red[128 + tid] + red[192 + tid] + b3[n];
    }
}

extern "C" void kernel_launch(void* const* d_in, const int* in_sizes, int n_in,
                              void* d_out, int out_size)
{
    const float* state  = (const float*)d_in[0];
    const float* action = (const float*)d_in[1];
    const float* W1     = (const float*)d_in[2];
    const float* b1     = (const float*)d_in[3];
    const float* W2     = (const float*)d_in[4];
    const float* b2     = (const float*)d_in[5];
    const float* W3     = (const float*)d_in[6];
    const float* b3     = (const float*)d_in[7];
    float* out = (float*)d_out;

    prep_x_kernel<<<NTILES, 256>>>(state, action);
    prep_w1_kernel<<<NQ * 4, 256>>>(W1);
    prep_w2_kernel<<<NQ * 8, 256>>>(W2);

    cudaFuncSetAttribute(qens_hmma_kernel,
                         cudaFuncAttributeMaxDynamicSharedMemorySize, SM_TOTAL);
    dim3 grid(NTILES, NQ);
    qens_hmma_kernel<<<grid, 256, SM_TOTAL>>>(b1, b2, W3, b3, out);
}